// round 17
// baseline (speedup 1.0000x reference)
#include <cuda_runtime.h>
#include <cuda_fp16.h>
#include <cstdint>

#define NF   128
#define HID  256
#define NTH  256
#define BM   64

// K-chunk = 32. smem layout (bytes), all regions DISJOINT:
//  A  : 2 x [64r][32k] pitch 40 halves  -> 2*5120  = 10240
//  H  : [64r][256k] pitch 264 halves    -> 33792
//  B1 : 3 x 16KB fragment-order chunks  -> 49152
//  B2 : 2 x 8KB  fragment-order chunks  -> 16384
#define AW     40
#define HWD    264
#define A_SZB  5120
#define OFF_H  10240
#define OFF_B1 44032
#define OFF_B2 93184
#define SMEM_BYTES 109568          // x2 CTAs = 219136 <= SM smem

// fragment-ordered weights (from prep):
// g_W1F[wn(4)][c64(6)][s(4)][q(4)][lane(32)] uint4 ; g_W2F[wn(4)][c64(4)][s(4)][q(2)][lane(32)]
__device__ uint4 g_W1F[4 * 6 * 4 * 4 * 32];   // 12288
__device__ uint4 g_W2F[4 * 4 * 4 * 2 * 32];   // 4096

// ---------------------------------------------------------------------------
static __device__ __forceinline__ uint32_t s2u(const void* p){
    uint32_t a;
    asm("{ .reg .u64 t; cvta.to.shared.u64 t, %1; cvt.u32.u64 %0, t; }" : "=r"(a) : "l"(p));
    return a;
}
static __device__ __forceinline__ void cp16(uint32_t d, const void* g){
    asm volatile("cp.async.ca.shared.global [%0], [%1], 16;" :: "r"(d), "l"(g) : "memory");
}
static __device__ __forceinline__ void cp_commit(){
    asm volatile("cp.async.commit_group;" ::: "memory");
}
static __device__ __forceinline__ void cp_wait1(){
    asm volatile("cp.async.wait_group 1;" ::: "memory");
}
static __device__ __forceinline__ void cp_wait0(){
    asm volatile("cp.async.wait_group 0;" ::: "memory");
}
static __device__ __forceinline__ void ldsm4(uint32_t* r, uint32_t addr){
    asm volatile("ldmatrix.sync.aligned.m8n8.x4.shared.b16 {%0,%1,%2,%3}, [%4];"
        : "=r"(r[0]), "=r"(r[1]), "=r"(r[2]), "=r"(r[3]) : "r"(addr));
}
static __device__ __forceinline__ uint4 lds128(uint32_t addr){
    uint4 v;
    asm volatile("ld.shared.v4.b32 {%0,%1,%2,%3}, [%4];"
        : "=r"(v.x), "=r"(v.y), "=r"(v.z), "=r"(v.w) : "r"(addr));
    return v;
}
static __device__ __forceinline__ void mma16(float* c, const uint32_t* a,
                                             uint32_t b0, uint32_t b1){
    asm volatile("mma.sync.aligned.m16n8k16.row.col.f32.f16.f16.f32 "
        "{%0,%1,%2,%3}, {%4,%5,%6,%7}, {%8,%9}, {%0,%1,%2,%3};"
        : "+f"(c[0]), "+f"(c[1]), "+f"(c[2]), "+f"(c[3])
        : "r"(a[0]), "r"(a[1]), "r"(a[2]), "r"(a[3]), "r"(b0), "r"(b1));
}
static __device__ __forceinline__ uint32_t pack2(float x, float y){
    __half2 h = __floats2half2_rn(x, y);
    return *reinterpret_cast<uint32_t*>(&h);
}

// ---------------------------------------------------------------------------
// prep: permute W1[384,256] / W2[256,128] (k-major fp32) into fragment order.
// ---------------------------------------------------------------------------
__global__ void prep_frag(const float* __restrict__ W1, const float* __restrict__ W2){
    const int i = blockIdx.x * blockDim.x + threadIdx.x;
    if (i < 12288){
        int lane = i & 31;
        int q = (i >> 5) & 3;
        int s = (i >> 7) & 3;
        int cw = i >> 9;               // wn*6 + c
        int c = cw % 6, wn = cw / 6;
        int n0 = wn * 64 + q * 16 + (lane >> 2);
        int k0 = c * 64 + s * 16 + 2 * (lane & 3);
        uint4 v;
        v.x = pack2(W1[(size_t)k0 * HID + n0],       W1[(size_t)(k0 + 1) * HID + n0]);
        v.y = pack2(W1[(size_t)(k0 + 8) * HID + n0], W1[(size_t)(k0 + 9) * HID + n0]);
        v.z = pack2(W1[(size_t)k0 * HID + n0 + 8],       W1[(size_t)(k0 + 1) * HID + n0 + 8]);
        v.w = pack2(W1[(size_t)(k0 + 8) * HID + n0 + 8], W1[(size_t)(k0 + 9) * HID + n0 + 8]);
        g_W1F[i] = v;
    } else if (i < 12288 + 4096){
        int j = i - 12288;
        int lane = j & 31;
        int q = (j >> 5) & 1;
        int s = (j >> 6) & 3;
        int c = (j >> 8) & 3;
        int wn = (j >> 10) & 3;
        int n0 = wn * 32 + q * 16 + (lane >> 2);
        int k0 = c * 64 + s * 16 + 2 * (lane & 3);
        uint4 v;
        v.x = pack2(W2[(size_t)k0 * NF + n0],       W2[(size_t)(k0 + 1) * NF + n0]);
        v.y = pack2(W2[(size_t)(k0 + 8) * NF + n0], W2[(size_t)(k0 + 9) * NF + n0]);
        v.z = pack2(W2[(size_t)k0 * NF + n0 + 8],       W2[(size_t)(k0 + 1) * NF + n0 + 8]);
        v.w = pack2(W2[(size_t)(k0 + 8) * NF + n0 + 8], W2[(size_t)(k0 + 9) * NF + n0 + 8]);
        g_W2F[j] = v;
    }
}

// ---------------------------------------------------------------------------
// fused edge-MLP: out = relu([src,dst,edge] @ W1 + b1) @ W2 + b2 + edge
// BM=64, 8 warps, 2 CTAs/SM. B via cp.async in fragment order (LDS.128 reads).
// ---------------------------------------------------------------------------
__global__ void __launch_bounds__(NTH, 2)
edge_mlp_h11(const float* __restrict__ src, const float* __restrict__ dst,
             const float* __restrict__ edg, const float* __restrict__ b1,
             const float* __restrict__ b2,  float* __restrict__ out, int E)
{
    extern __shared__ __half sh[];
    const uint32_t sb = s2u(sh);
    __half* Ah = sh;                                 // 2 x A_SZB

    const int tid  = threadIdx.x;
    const int lane = tid & 31, wid = tid >> 5;
    const int g = lane >> 2, t = lane & 3;
    const int row0 = blockIdx.x * BM;

    const int rb = (wid & 1) * 32;                   // M row base (both phases)
    const int wn = wid >> 1;                         // N group 0..3
    const bool prod = (wid & 1) == 0;                // B producer warp of the pair

    // ---- A staging: chunk32 c = 0..11 ----
    auto ldgA = [&](int c, float4* v){
        const float* xp = (c < 4) ? src : (c < 8) ? dst : edg;
        const int cb = (c & 3) * 32;
#pragma unroll
        for (int i = 0; i < 2; i++){
            int lin = tid + i * NTH;                 // 0..511
            int kq = lin & 7, r = lin >> 3;
            int rg = row0 + r;
            v[i] = (rg < E) ? *reinterpret_cast<const float4*>(
                                  xp + (size_t)rg * NF + cb + kq * 4)
                            : make_float4(0.f, 0.f, 0.f, 0.f);
        }
    };
    auto stsA = [&](const float4* v, int buf){
        __half* d = Ah + buf * (A_SZB / 2);
#pragma unroll
        for (int i = 0; i < 2; i++){
            int lin = tid + i * NTH;
            int kq = lin & 7, r = lin >> 3;
            uint2 p;
            p.x = pack2(v[i].x, v[i].y);
            p.y = pack2(v[i].z, v[i].w);
            *reinterpret_cast<uint2*>(d + r * AW + kq * 4) = p;
        }
    };

    // ---- B producers (fragment-order cp.async, per wn-pair) ----
    auto prodB1 = [&](int c, int buf){               // 8 fragments x 512B
        if (prod){
            const uint32_t d = sb + OFF_B1 + (uint32_t)buf * 16384
                             + (uint32_t)(wn * 8) * 512 + lane * 16;
            const uint4* s0 = g_W1F + (size_t)(wn * 96 + c * 8) * 32 + lane;
#pragma unroll
            for (int f = 0; f < 8; f++)
                cp16(d + f * 512, s0 + (size_t)f * 32);
        }
    };
    auto prodB2 = [&](int c, int buf){               // 4 fragments x 512B
        if (prod){
            const uint32_t d = sb + OFF_B2 + (uint32_t)buf * 8192
                             + (uint32_t)(wn * 4) * 512 + lane * 16;
            const uint4* s0 = g_W2F + (size_t)(wn * 32 + c * 4) * 32 + lane;
#pragma unroll
            for (int f = 0; f < 4; f++)
                cp16(d + f * 512, s0 + (size_t)f * 32);
        }
    };

    // =================== phase 1: D1 = X @ W1  (K=384, 12 chunks) ==========
    const int nb = wn * 64;
    const uint32_t aOff = (uint32_t)(((rb + (lane & 15)) * AW + (lane >> 4) * 8)) * 2;
    const uint32_t b1Off = (uint32_t)(wn * 8) * 512 + lane * 16;

    float acc[2][8][4];
#pragma unroll
    for (int ma = 0; ma < 2; ma++)
#pragma unroll
        for (int na = 0; na < 8; na++)
#pragma unroll
            for (int q = 0; q < 4; q++) acc[ma][na][q] = 0.f;

    float4 av[2];
    ldgA(0, av); stsA(av, 0);
    ldgA(1, av);
    prodB1(0, 0); cp_commit();
    prodB1(1, 1); cp_commit();

    for (int c = 0; c < 12; c++){
        const int p = c & 1;
        if (c < 11) cp_wait1(); else cp_wait0();     // B1 chunk c landed
        __syncthreads();                             // visibility + A buf ready
        if (c < 10){ prodB1(c + 2, (c + 2) % 3); cp_commit(); }
        const uint32_t aB = sb + (uint32_t)(p * A_SZB) + aOff;
        const uint32_t bB = sb + OFF_B1 + (uint32_t)((c % 3) * 16384) + b1Off;
#pragma unroll
        for (int s = 0; s < 2; s++){
            uint32_t a[2][4];
#pragma unroll
            for (int ma = 0; ma < 2; ma++)
                ldsm4(a[ma], aB + (uint32_t)(ma * 16 * AW) * 2 + s * 32);
            uint4 v0 = lds128(bB + (s * 4 + 0) * 512);
            uint4 v1 = lds128(bB + (s * 4 + 1) * 512);
            uint4 v2 = lds128(bB + (s * 4 + 2) * 512);
            uint4 v3 = lds128(bB + (s * 4 + 3) * 512);
#pragma unroll
            for (int ma = 0; ma < 2; ma++){
                mma16(acc[ma][0], a[ma], v0.x, v0.y);
                mma16(acc[ma][1], a[ma], v0.z, v0.w);
                mma16(acc[ma][2], a[ma], v1.x, v1.y);
                mma16(acc[ma][3], a[ma], v1.z, v1.w);
                mma16(acc[ma][4], a[ma], v2.x, v2.y);
                mma16(acc[ma][5], a[ma], v2.z, v2.w);
                mma16(acc[ma][6], a[ma], v3.x, v3.y);
                mma16(acc[ma][7], a[ma], v3.z, v3.w);
            }
            if (c < 11){
                if (s == 0) stsA(av, p ^ 1);         // chunk c+1 -> free A buf
                else if (c < 10) ldgA(c + 2, av);
            }
        }
    }

    // ====== epilogue 1: H = half(relu(D1 + b1)) -> smem (disjoint) =========
    prodB2(0, 0); cp_commit();
    __half* Hh = sh + OFF_H / 2;
#pragma unroll
    for (int na = 0; na < 8; na++){
        const int col = nb + na * 8 + 2 * t;
        const float2 bvv = *reinterpret_cast<const float2*>(b1 + col);
#pragma unroll
        for (int ma = 0; ma < 2; ma++){
            const int r0 = rb + ma * 16 + g;
            *reinterpret_cast<uint32_t*>(Hh + r0 * HWD + col) =
                pack2(fmaxf(acc[ma][na][0] + bvv.x, 0.f),
                      fmaxf(acc[ma][na][1] + bvv.y, 0.f));
            *reinterpret_cast<uint32_t*>(Hh + (r0 + 8) * HWD + col) =
                pack2(fmaxf(acc[ma][na][2] + bvv.x, 0.f),
                      fmaxf(acc[ma][na][3] + bvv.y, 0.f));
        }
    }
    prodB2(1, 1); cp_commit();

    // =================== phase 2: D2 = H @ W2  (K=256, 8 chunks) ===========
    const int nb2 = wn * 32;
    const uint32_t aOff2 = (uint32_t)(((rb + (lane & 15)) * HWD + (lane >> 4) * 8)) * 2;
    const uint32_t b2Off = (uint32_t)(wn * 4) * 512 + lane * 16;

    float ac2[2][4][4];
#pragma unroll
    for (int ma = 0; ma < 2; ma++)
#pragma unroll
        for (int na = 0; na < 4; na++)
#pragma unroll
            for (int q = 0; q < 4; q++) ac2[ma][na][q] = 0.f;

    for (int c2 = 0; c2 < 8; c2++){
        const int pb = c2 & 1;
        if (c2 < 7) cp_wait1(); else cp_wait0();     // B2 chunk c2 landed
        __syncthreads();                             // H + B2 visible
        const uint32_t aB = sb + OFF_H + aOff2 + (uint32_t)(c2 * 64);
        const uint32_t bB = sb + OFF_B2 + (uint32_t)(pb * 8192) + b2Off;
#pragma unroll
        for (int s = 0; s < 2; s++){
            uint32_t a[2][4];
#pragma unroll
            for (int ma = 0; ma < 2; ma++)
                ldsm4(a[ma], aB + (uint32_t)(ma * 16 * HWD) * 2 + s * 32);
            uint4 v0 = lds128(bB + (s * 2 + 0) * 512);
            uint4 v1 = lds128(bB + (s * 2 + 1) * 512);
#pragma unroll
            for (int ma = 0; ma < 2; ma++){
                mma16(ac2[ma][0], a[ma], v0.x, v0.y);
                mma16(ac2[ma][1], a[ma], v0.z, v0.w);
                mma16(ac2[ma][2], a[ma], v1.x, v1.y);
                mma16(ac2[ma][3], a[ma], v1.z, v1.w);
            }
        }
        if (c2 < 6){
            __syncthreads();                         // pair's reads of buf pb done
            prodB2(c2 + 2, pb); cp_commit();
        }
    }

    // ========= epilogue 2: out = D2 + b2 + edge residual (guarded) =========
#pragma unroll
    for (int ma = 0; ma < 2; ma++){
#pragma unroll
        for (int half = 0; half < 2; half++){
            const int rg = row0 + rb + ma * 16 + g + half * 8;
            if (rg < E){
#pragma unroll
                for (int na = 0; na < 4; na++){
                    const int col = nb2 + na * 8 + 2 * t;
                    const float2 bvv = *reinterpret_cast<const float2*>(b2 + col);
                    const float2 ea = *reinterpret_cast<const float2*>(
                                          edg + (size_t)rg * NF + col);
                    float2 v;
                    v.x = ac2[ma][na][half * 2 + 0] + bvv.x + ea.x;
                    v.y = ac2[ma][na][half * 2 + 1] + bvv.y + ea.y;
                    *reinterpret_cast<float2*>(out + (size_t)rg * NF + col) = v;
                }
            }
        }
    }
}

// ---------------------------------------------------------------------------
// inputs: 0=src 1=dest 2=edge_attr 3=u(unused) 4=batch(unused) 5=W1 6=b1 7=W2 8=b2
// ---------------------------------------------------------------------------
extern "C" void kernel_launch(void* const* d_in, const int* in_sizes, int n_in,
                              void* d_out, int out_size)
{
    const float* src  = (const float*)d_in[0];
    const float* dst  = (const float*)d_in[1];
    const float* edge = (const float*)d_in[2];
    const float* W1   = (const float*)d_in[5];
    const float* b1   = (const float*)d_in[6];
    const float* W2   = (const float*)d_in[7];
    const float* b2   = (const float*)d_in[8];
    float* out = (float*)d_out;

    const int E = in_sizes[0] / NF;

    prep_frag<<<(12288 + 4096 + 255) / 256, 256>>>(W1, W2);

    cudaFuncSetAttribute(edge_mlp_h11,
                         cudaFuncAttributeMaxDynamicSharedMemorySize, SMEM_BYTES);
    const int grid = (E + BM - 1) / BM;
    edge_mlp_h11<<<grid, NTH, SMEM_BYTES>>>(src, dst, edge, b1, b2, out, E);
}